// round 2
// baseline (speedup 1.0000x reference)
#include <cuda_runtime.h>

#define NB      32768
#define DIN     784
#define DH      512
#define DOUT    10
#define NSTEPS  25
#define BETA    0.9f
#define THR     1.0f

// 64 MB scratch for cur1 = x @ W1^T + b1  (static __device__ => allowed)
__device__ float g_cur1[(size_t)NB * DH];

// ---------------------------------------------------------------------------
// Kernel 1: fp32 GEMM  g_cur1[m][n] = b1[n] + sum_k x[m][k] * W1[n][k]
// M=32768, N=512, K=784. Tiles 128x128x16, 256 threads, 8x8 micro-tile,
// double-buffered shared memory.
// ---------------------------------------------------------------------------
__global__ __launch_bounds__(256, 2)
void gemm1_kernel(const float* __restrict__ X,
                  const float* __restrict__ W1,
                  const float* __restrict__ b1)
{
    __shared__ float As[2][16][132];   // [k][m], padded to 132 to dodge conflicts
    __shared__ float Bs[2][16][132];   // [k][n]

    const int tid = threadIdx.x;
    const int bm  = blockIdx.y * 128;
    const int bn  = blockIdx.x * 128;

    // load mapping: each thread loads 8 consecutive floats (2x float4) of one row
    const int lm = tid >> 1;           // 0..127 (tile row)
    const int lk = (tid & 1) * 8;      // 0 or 8 (k offset)

    // compute mapping
    const int ty = tid >> 4;           // 0..15 -> m sub-tile (8 rows)
    const int tx = tid & 15;           // 0..15 -> n sub-tile (8 cols)

    const float* aptr = X  + (size_t)(bm + lm) * DIN + lk;
    const float* bptr = W1 + (size_t)(bn + lm) * DIN + lk;

    float4 ar0, ar1, br0, br1;

    // preload k-tile 0
    ar0 = *(const float4*)(aptr + 0);
    ar1 = *(const float4*)(aptr + 4);
    br0 = *(const float4*)(bptr + 0);
    br1 = *(const float4*)(bptr + 4);
    #pragma unroll
    for (int q = 0; q < 4; q++) {
        As[0][lk + q][lm]     = ((const float*)&ar0)[q];
        As[0][lk + 4 + q][lm] = ((const float*)&ar1)[q];
        Bs[0][lk + q][lm]     = ((const float*)&br0)[q];
        Bs[0][lk + 4 + q][lm] = ((const float*)&br1)[q];
    }
    __syncthreads();

    float acc[8][8];
    #pragma unroll
    for (int i = 0; i < 8; i++)
        #pragma unroll
        for (int j = 0; j < 8; j++) acc[i][j] = 0.f;

    int buf = 0;
    const int NKT = DIN / 16;          // 49
    for (int kt = 0; kt < NKT; kt++) {
        if (kt + 1 < NKT) {
            const float* ap = aptr + (kt + 1) * 16;
            const float* bp = bptr + (kt + 1) * 16;
            ar0 = *(const float4*)(ap);
            ar1 = *(const float4*)(ap + 4);
            br0 = *(const float4*)(bp);
            br1 = *(const float4*)(bp + 4);
        }
        #pragma unroll
        for (int k = 0; k < 16; k++) {
            float a[8], b[8];
            *(float4*)(a)     = *(const float4*)(&As[buf][k][ty * 8]);
            *(float4*)(a + 4) = *(const float4*)(&As[buf][k][ty * 8 + 4]);
            *(float4*)(b)     = *(const float4*)(&Bs[buf][k][tx * 8]);
            *(float4*)(b + 4) = *(const float4*)(&Bs[buf][k][tx * 8 + 4]);
            #pragma unroll
            for (int i = 0; i < 8; i++)
                #pragma unroll
                for (int j = 0; j < 8; j++)
                    acc[i][j] += a[i] * b[j];
        }
        if (kt + 1 < NKT) {
            const int nb = buf ^ 1;
            #pragma unroll
            for (int q = 0; q < 4; q++) {
                As[nb][lk + q][lm]     = ((const float*)&ar0)[q];
                As[nb][lk + 4 + q][lm] = ((const float*)&ar1)[q];
                Bs[nb][lk + q][lm]     = ((const float*)&br0)[q];
                Bs[nb][lk + 4 + q][lm] = ((const float*)&br1)[q];
            }
        }
        __syncthreads();
        buf ^= 1;
    }

    // epilogue: add bias, store
    float bias[8];
    #pragma unroll
    for (int j = 0; j < 8; j++) bias[j] = b1[bn + tx * 8 + j];

    #pragma unroll
    for (int i = 0; i < 8; i++) {
        float* crow = g_cur1 + (size_t)(bm + ty * 8 + i) * DH + bn + tx * 8;
        float4 v0, v1;
        v0.x = acc[i][0] + bias[0];
        v0.y = acc[i][1] + bias[1];
        v0.z = acc[i][2] + bias[2];
        v0.w = acc[i][3] + bias[3];
        v1.x = acc[i][4] + bias[4];
        v1.y = acc[i][5] + bias[5];
        v1.z = acc[i][6] + bias[6];
        v1.w = acc[i][7] + bias[7];
        *(float4*)(crow)     = v0;
        *(float4*)(crow + 4) = v1;
    }
}

// ---------------------------------------------------------------------------
// Kernel 2: fused 25-step SNN recurrence. One warp owns TWO batch rows.
// cur1/mem1 live in registers (neuron n = i*32 + lane), W2 in smem [j][n]
// (stride-1, conflict-free). Spikes are 0/1 -> predicated FADD (no FMUL).
// Lanes 0..9 carry mem2[j] and write spk_rec/mem_rec ([25, B, 10] each,
// spk_rec first then mem_rec in d_out).
// ---------------------------------------------------------------------------
__global__ __launch_bounds__(256)
void snn_kernel(const float* __restrict__ W2,
                const float* __restrict__ b2,
                float* __restrict__ out)
{
    __shared__ float w2s[DOUT][DH];    // [j][n] : W2 is [10,512] row-major, same layout
    for (int idx = threadIdx.x; idx < DOUT * DH; idx += 256)
        ((float*)w2s)[idx] = W2[idx];
    __syncthreads();

    const int warp = threadIdx.x >> 5;
    const int lane = threadIdx.x & 31;
    const int row0 = (blockIdx.x * 8 + warp) * 2;
    const int row1 = row0 + 1;

    float cur1a[16], cur1b[16], mem1a[16], mem1b[16];
    const float* ca = g_cur1 + (size_t)row0 * DH + lane;
    const float* cb = g_cur1 + (size_t)row1 * DH + lane;
    #pragma unroll
    for (int i = 0; i < 16; i++) {
        cur1a[i] = ca[i * 32];
        cur1b[i] = cb[i * 32];
        mem1a[i] = 0.f;
        mem1b[i] = 0.f;
    }

    float mem2a = 0.f, mem2b = 0.f;
    const float b2v = (lane < DOUT) ? b2[lane] : 0.f;
    const size_t MEMOFF = (size_t)NSTEPS * NB * DOUT;   // spk_rec size

    for (int t = 0; t < NSTEPS; t++) {
        float part[20];
        #pragma unroll
        for (int j = 0; j < 20; j++) part[j] = 0.f;

        #pragma unroll
        for (int i = 0; i < 16; i++) {
            // layer-1 LIF update (reset uses PREVIOUS mem, spike uses NEW mem)
            float ma = mem1a[i];
            ma = BETA * ma + cur1a[i] - ((ma > THR) ? THR : 0.f);
            mem1a[i] = ma;
            const bool sa = ma > THR;

            float mb = mem1b[i];
            mb = BETA * mb + cur1b[i] - ((mb > THR) ? THR : 0.f);
            mem1b[i] = mb;
            const bool sb = mb > THR;

            const int n = i * 32 + lane;
            #pragma unroll
            for (int j = 0; j < DOUT; j++) {
                const float w = w2s[j][n];       // one LDS serves both rows
                if (sa) part[j]      += w;
                if (sb) part[10 + j] += w;
            }
        }

        // butterfly reduce all 20 partials across the warp
        #pragma unroll
        for (int off = 16; off > 0; off >>= 1)
            #pragma unroll
            for (int j = 0; j < 20; j++)
                part[j] += __shfl_xor_sync(0xffffffffu, part[j], off);

        if (lane < DOUT) {
            const float c2a = part[lane] + b2v;
            const float c2b = part[10 + lane] + b2v;
            const float na = BETA * mem2a + c2a - ((mem2a > THR) ? THR : 0.f);
            const float nb = BETA * mem2b + c2b - ((mem2b > THR) ? THR : 0.f);
            mem2a = na;
            mem2b = nb;
            const float ska = (na > THR) ? 1.f : 0.f;
            const float skb = (nb > THR) ? 1.f : 0.f;

            const size_t base = (size_t)t * NB * DOUT;
            out[base + (size_t)row0 * DOUT + lane]          = ska;
            out[base + (size_t)row1 * DOUT + lane]          = skb;
            out[MEMOFF + base + (size_t)row0 * DOUT + lane] = na;
            out[MEMOFF + base + (size_t)row1 * DOUT + lane] = nb;
        }
    }
}

// ---------------------------------------------------------------------------
extern "C" void kernel_launch(void* const* d_in, const int* in_sizes, int n_in,
                              void* d_out, int out_size)
{
    (void)in_sizes; (void)n_in; (void)out_size;
    const float* x  = (const float*)d_in[0];   // [32768, 784]
    const float* W1 = (const float*)d_in[1];   // [512, 784]
    const float* b1 = (const float*)d_in[2];   // [512]
    const float* W2 = (const float*)d_in[3];   // [10, 512]
    const float* b2 = (const float*)d_in[4];   // [10]
    float* out = (float*)d_out;                // [2, 25, 32768, 10]

    dim3 ggrid(DH / 128, NB / 128);            // (4, 256)
    gemm1_kernel<<<ggrid, 256>>>(x, W1, b1);

    const int rows_per_block = 8 * 2;          // 8 warps x 2 rows
    snn_kernel<<<NB / rows_per_block, 256>>>(W2, b2, out);
}